// round 10
// baseline (speedup 1.0000x reference)
#include <cuda_runtime.h>
#include <cstdint>

#define N_   32
#define C_   256
#define O_   256
#define HW_  56
#define PIX  3136
#define NPIX (N_ * PIX)          // 100352 = 784 * 128
#define CNTS 802816.0f
#define EPSF 1e-5f

// ---------------- device scratch ----------------
__device__ float g_asum[N_];
__device__ float g_m[O_];
__device__ __align__(16) signed char g_xb[(size_t)NPIX * C_];   // int8 +-1, [n*PIX+p][c]
__device__ __align__(16) signed char g_wb[9 * O_ * C_];         // int8 +-1, [tap][o][c]
__device__ int g_xz_count;
__device__ int g_wz_count;
__device__ int g_xz_list[4096];
__device__ int g_wz_list[64];

__device__ __forceinline__ float alpha_of(int n) {
    return fmaxf(2.f * g_asum[n] / CNTS, EPSF);
}

__device__ __forceinline__ void imma16832(int* c, const unsigned* a, const unsigned* b) {
    asm volatile(
        "mma.sync.aligned.m16n8k32.row.col.s32.s8.s8.s32 "
        "{%0,%1,%2,%3}, {%4,%5,%6,%7}, {%8,%9}, {%0,%1,%2,%3};"
        : "+r"(c[0]), "+r"(c[1]), "+r"(c[2]), "+r"(c[3])
        : "r"(a[0]), "r"(a[1]), "r"(a[2]), "r"(a[3]), "r"(b[0]), "r"(b[1]));
}

// ---------------- K0 ----------------
__global__ void k_zero() {
    int t = blockIdx.x * blockDim.x + threadIdx.x;
    if (t < N_) g_asum[t] = 0.f;
    if (t == 0) { g_xz_count = 0; g_wz_count = 0; }
}

// ---------------- K1: pack x -> int8 +-1 NHWC + sum|x| + zero list ----------------
__global__ void k_packx(const float* __restrict__ x) {
    int b   = blockIdx.x;
    int n   = b & 31;
    int pix = (b >> 5) * 256 + threadIdx.x;
    int tid = threadIdx.x;

    float s = 0.f;
    if (pix < PIX) {
        const float* base = x + (size_t)n * C_ * PIX + pix;
        signed char* dst = &g_xb[((size_t)n * PIX + pix) * C_];
#pragma unroll 2
        for (int c16 = 0; c16 < 16; c16++) {
            signed char u[16];
#pragma unroll
            for (int j = 0; j < 16; j++) {
                int ch = c16 * 16 + j;
                float v = base[(size_t)ch * PIX];
                s += fabsf(v);
                u[j] = (v < 0.f) ? (signed char)-1 : (signed char)1;
                if (v == 0.f) {
                    int idx = atomicAdd(&g_xz_count, 1);
                    if (idx < 4096) g_xz_list[idx] = (n * C_ + ch) * PIX + pix;
                }
            }
            *(uint4*)&dst[c16 * 16] = *(const uint4*)u;
        }
    }

    __shared__ float red[256];
    red[tid] = s;
    __syncthreads();
    for (int st = 128; st > 0; st >>= 1) {
        if (tid < st) red[tid] += red[tid + st];
        __syncthreads();
    }
    if (tid == 0) atomicAdd(&g_asum[n], red[0]);
}

// ---------------- K2: pack w -> int8 +-1 [tap][o][c] + m[o] + zero list ----------------
__global__ void k_packw(const float* __restrict__ w) {
    int o = blockIdx.x;
    int c = threadIdx.x;

    float s = 0.f;
#pragma unroll
    for (int tap = 0; tap < 9; tap++) {
        float v = w[((size_t)(o * C_ + c)) * 9 + tap];
        s += fabsf(v);
        g_wb[((size_t)tap * O_ + o) * C_ + c] = (v < 0.f) ? (signed char)-1 : (signed char)1;
        if (v == 0.f) {
            int idx = atomicAdd(&g_wz_count, 1);
            if (idx < 64) g_wz_list[idx] = (o * C_ + c) * 9 + tap;
        }
    }
    __shared__ float red[256];
    red[c] = s;
    __syncthreads();
    for (int st = 128; st > 0; st >>= 1) {
        if (c < st) red[c] += red[c + st];
        __syncthreads();
    }
    if (c == 0) g_m[o] = red[0] / 2304.f;
}

// ---------------- K3: int8 mma.sync implicit-GEMM conv ----------------
// CTA 128(M)x128(N); grid = 784 mtiles * 2 nhalves = 1568; 256 thr, 8 warps (2Mx4N).
// SMEM: A 128x(256B + 16 pad) + B 128x(256B + 16 pad) = 69632 B, row stride 68 words.
#define RS   68                       // row stride in words
#define A_WORDS (128 * RS)            // 8704
#define CONV_SMEM (2 * 128 * RS * 4)  // 69632

__global__ __launch_bounds__(256, 2) void k_conv(float* __restrict__ out) {
    extern __shared__ unsigned smw[];
    unsigned* As = smw;
    unsigned* Bs = smw + A_WORDS;

    int tid  = threadIdx.x;
    int wid  = tid >> 5;
    int lane = tid & 31;
    int g    = lane >> 2;
    int tig  = lane & 3;

    int mBase = (blockIdx.x >> 1) * 128;
    int nBase = (blockIdx.x & 1) * 128;

    // fill-role mapping
    int pix_i = tid >> 1;
    int half  = tid & 1;
    int gp = mBase + pix_i;
    int fn = gp / PIX;
    int fp = gp - fn * PIX;
    int fh = fp / HW_, fw = fp - (fp / HW_) * HW_;

    int m_off = (wid & 1) * 64;
    int n_off = (wid >> 1) * 32;

    int acc[4][4][4];
#pragma unroll
    for (int mi = 0; mi < 4; mi++)
#pragma unroll
        for (int ni = 0; ni < 4; ni++)
#pragma unroll
            for (int k = 0; k < 4; k++) acc[mi][ni][k] = 0;

    const uint4 z4 = make_uint4(0u, 0u, 0u, 0u);

#pragma unroll 1
    for (int tap = 0; tap < 9; tap++) {
        if (tap) __syncthreads();

        // --- fill A (gathered, zero halo) and B (contiguous) ---
        int dh = tap / 3 - 1, dw = tap % 3 - 1;
        int h2 = fh + dh, w2 = fw + dw;
        bool valid = ((unsigned)h2 < HW_) && ((unsigned)w2 < HW_);
        const uint4* srcA = (const uint4*)&g_xb[((size_t)fn * PIX + h2 * HW_ + w2) * C_ + half * 128];
        const uint4* srcB = (const uint4*)&g_wb[((size_t)tap * O_ + nBase + pix_i) * C_ + half * 128];
#pragma unroll
        for (int j = 0; j < 8; j++) {
            *(uint4*)&As[pix_i * RS + half * 32 + j * 4] = valid ? srcA[j] : z4;
            *(uint4*)&Bs[pix_i * RS + half * 32 + j * 4] = srcB[j];
        }
        __syncthreads();

        // --- compute: 8 k32 chunks ---
#pragma unroll 1
        for (int kc = 0; kc < 8; kc++) {
            unsigned a[4][4], bfr[4][2];
            int kw0 = kc * 8 + tig;
#pragma unroll
            for (int mi = 0; mi < 4; mi++) {
                int base = (m_off + mi * 16 + g) * RS + kw0;
                a[mi][0] = As[base];
                a[mi][1] = As[base + 8 * RS];
                a[mi][2] = As[base + 4];
                a[mi][3] = As[base + 8 * RS + 4];
            }
#pragma unroll
            for (int ni = 0; ni < 4; ni++) {
                int base = (n_off + ni * 8 + g) * RS + kw0;
                bfr[ni][0] = Bs[base];
                bfr[ni][1] = Bs[base + 4];
            }
#pragma unroll
            for (int mi = 0; mi < 4; mi++)
#pragma unroll
                for (int ni = 0; ni < 4; ni++)
                    imma16832(acc[mi][ni], a[mi], bfr[ni]);
        }
    }

    // ---------------- epilogue: scale and store ----------------
#pragma unroll
    for (int mi = 0; mi < 4; mi++) {
        int r0 = m_off + mi * 16 + g;
        int gp0 = mBase + r0;
        int n0 = gp0 / PIX, p0 = gp0 - n0 * PIX;
        int gp1 = gp0 + 8;
        int n1 = gp1 / PIX, p1 = gp1 - n1 * PIX;
        float al0 = alpha_of(n0);
        float al1 = alpha_of(n1);
#pragma unroll
        for (int ni = 0; ni < 4; ni++) {
            int o0 = nBase + n_off + ni * 8 + tig * 2;
            float m0 = __ldg(&g_m[o0]);
            float m1 = __ldg(&g_m[o0 + 1]);
            out[((size_t)(n0 * O_ + o0)) * PIX + p0]     = al0 * m0 * (float)acc[mi][ni][0];
            out[((size_t)(n0 * O_ + o0 + 1)) * PIX + p0] = al0 * m1 * (float)acc[mi][ni][1];
            out[((size_t)(n1 * O_ + o0)) * PIX + p1]     = al1 * m0 * (float)acc[mi][ni][2];
            out[((size_t)(n1 * O_ + o0 + 1)) * PIX + p1] = al1 * m1 * (float)acc[mi][ni][3];
        }
    }
}

// ---------------- K4: exact correction for x==0 ----------------
__global__ void k_xzero(float* __restrict__ out) {
    int zc = g_xz_count;
    if (zc > 4096) zc = 4096;
    long total = (long)zc * 2304;
    for (long i = (long)blockIdx.x * blockDim.x + threadIdx.x; i < total;
         i += (long)gridDim.x * blockDim.x) {
        int z = (int)(i / 2304);
        int q = (int)(i % 2304);
        int o = q / 9, tap = q % 9;
        int li = g_xz_list[z];
        int pix = li % PIX;
        int ch = (li / PIX) & 255;
        int n = li / (PIX * C_);
        int h = pix / HW_, wv = pix % HW_;
        int kh = tap / 3, kw = tap % 3;
        int oh = h + 1 - kh, ow = wv + 1 - kw;
        if ((unsigned)oh < HW_ && (unsigned)ow < HW_) {
            float bw = (float)g_wb[((size_t)tap * O_ + o) * C_ + ch];  // encoded +-1
            atomicAdd(&out[((size_t)(n * O_ + o)) * PIX + oh * HW_ + ow],
                      -bw * alpha_of(n) * g_m[o]);
        }
    }
}

// ---------------- K5: exact correction for w==0 ----------------
__global__ void k_wzero(const float* __restrict__ x, float* __restrict__ out) {
    int zc = g_wz_count;
    if (zc > 64) zc = 64;
    long total = (long)zc * N_ * PIX;
    for (long i = (long)blockIdx.x * blockDim.x + threadIdx.x; i < total;
         i += (long)gridDim.x * blockDim.x) {
        int z = (int)(i / ((long)N_ * PIX));
        int rte = (int)(i % ((long)N_ * PIX));
        int n = rte / PIX, pix = rte % PIX;
        int oh = pix / HW_, ow = pix % HW_;
        int li = g_wz_list[z];
        int tap = li % 9;
        int ch = (li / 9) & 255;
        int o = li / (9 * C_);
        int kh = tap / 3, kw = tap % 3;
        int ih = oh - 1 + kh, iw = ow - 1 + kw;
        if ((unsigned)ih < HW_ && (unsigned)iw < HW_) {
            float xv = x[((size_t)(n * C_ + ch)) * PIX + ih * HW_ + iw];
            if (xv != 0.f) {               // x==0 already fixed by k_xzero
                float bx = (xv < 0.f) ? -1.f : 1.f;
                atomicAdd(&out[((size_t)(n * O_ + o)) * PIX + pix],
                          -bx * alpha_of(n) * g_m[o]);
            }
        }
    }
}

// ---------------- launch ----------------
extern "C" void kernel_launch(void* const* d_in, const int* in_sizes, int n_in,
                              void* d_out, int out_size) {
    const float* x = (const float*)d_in[0];
    const float* w = (const float*)d_in[1];
    float* out = (float*)d_out;

    cudaFuncSetAttribute(k_conv, cudaFuncAttributeMaxDynamicSharedMemorySize, CONV_SMEM);

    k_zero<<<9, 256>>>();
    k_packx<<<416, 256>>>(x);
    k_packw<<<256, 256>>>(w);
    k_conv<<<1568, 256, CONV_SMEM>>>(out);
    k_xzero<<<64, 256>>>(out);
    k_wzero<<<128, 256>>>(x, out);
}

// round 11
// speedup vs baseline: 1.9342x; 1.9342x over previous
#include <cuda_runtime.h>
#include <cstdint>

#define N_   32
#define C_   256
#define O_   256
#define HW_  56
#define PIX  3136
#define NPIX (N_ * PIX)          // 100352 = 784 * 128
#define CNTS 802816.0f
#define EPSF 1e-5f

// ---------------- device scratch ----------------
__device__ float g_asum[N_];
__device__ float g_m[O_];
__device__ __align__(16) signed char g_xb[(size_t)NPIX * C_];     // int8 +-1 [pix][c]
__device__ __align__(16) signed char g_wb[9 * O_ * C_];           // int8 +-1 [tap][o][c]
__device__ __align__(16) unsigned g_xbits[(size_t)NPIX * 8];      // bitpacked [pix][8w]
__device__ __align__(16) unsigned g_wt[9 * 8 * O_];               // bitpacked [tap][w8][o]
__device__ int g_pw[O_ * 9];                                      // popc per (o,tap)
__device__ int g_xz_count;
__device__ int g_wz_count;
__device__ int g_xz_list[4096];
__device__ int g_wz_list[64];

__device__ __forceinline__ float alpha_of(int n) {
    return fmaxf(2.f * g_asum[n] / CNTS, EPSF);
}

__device__ __forceinline__ void imma16832(int* c, const unsigned* a, const unsigned* b) {
    asm volatile(
        "mma.sync.aligned.m16n8k32.row.col.s32.s8.s8.s32 "
        "{%0,%1,%2,%3}, {%4,%5,%6,%7}, {%8,%9}, {%0,%1,%2,%3};"
        : "+r"(c[0]), "+r"(c[1]), "+r"(c[2]), "+r"(c[3])
        : "r"(a[0]), "r"(a[1]), "r"(a[2]), "r"(a[3]), "r"(b[0]), "r"(b[1]));
}

// ---------------- K0 ----------------
__global__ void k_zero() {
    int t = blockIdx.x * blockDim.x + threadIdx.x;
    if (t < N_) g_asum[t] = 0.f;
    if (t == 0) { g_xz_count = 0; g_wz_count = 0; }
}

// ---------------- K1: pack x -> int8 +-1 NHWC, bitpacked, sum|x|, zero list ----------
__global__ void k_packx(const float* __restrict__ x) {
    int b   = blockIdx.x;
    int n   = b & 31;
    int pix = (b >> 5) * 256 + threadIdx.x;
    int tid = threadIdx.x;

    float s = 0.f;
    if (pix < PIX) {
        const float* base = x + (size_t)n * C_ * PIX + pix;
        signed char* dst = &g_xb[((size_t)n * PIX + pix) * C_];
        unsigned bw[8];
#pragma unroll
        for (int w8 = 0; w8 < 8; w8++) {
            unsigned bb = 0;
            signed char u[32];
#pragma unroll
            for (int j = 0; j < 32; j++) {
                int ch = w8 * 32 + j;
                float v = base[(size_t)ch * PIX];
                s += fabsf(v);
                bool neg = (v < 0.f);
                u[j] = neg ? (signed char)-1 : (signed char)1;
                bb |= ((unsigned)neg) << j;
                if (v == 0.f) {
                    int idx = atomicAdd(&g_xz_count, 1);
                    if (idx < 4096) g_xz_list[idx] = (n * C_ + ch) * PIX + pix;
                }
            }
            bw[w8] = bb;
            *(uint4*)&dst[w8 * 32]      = *(const uint4*)&u[0];
            *(uint4*)&dst[w8 * 32 + 16] = *(const uint4*)&u[16];
        }
        uint4* bd = (uint4*)&g_xbits[((size_t)n * PIX + pix) * 8];
        bd[0] = make_uint4(bw[0], bw[1], bw[2], bw[3]);
        bd[1] = make_uint4(bw[4], bw[5], bw[6], bw[7]);
    }

    __shared__ float red[256];
    red[tid] = s;
    __syncthreads();
    for (int st = 128; st > 0; st >>= 1) {
        if (tid < st) red[tid] += red[tid + st];
        __syncthreads();
    }
    if (tid == 0) atomicAdd(&g_asum[n], red[0]);
}

// ---------------- K2: pack w -> int8 [tap][o][c], bitpacked [tap][w8][o], pw, m ----
__global__ void k_packw(const float* __restrict__ w) {
    int o = blockIdx.x;
    int tid = threadIdx.x;
    int j = tid >> 5, lane = tid & 31;
    int c = j * 32 + lane;

    float s = 0.f;
#pragma unroll
    for (int tap = 0; tap < 9; tap++) {
        float v = w[((size_t)(o * C_ + c)) * 9 + tap];
        s += fabsf(v);
        bool neg = (v < 0.f);
        g_wb[((size_t)tap * O_ + o) * C_ + c] = neg ? (signed char)-1 : (signed char)1;
        unsigned bal = __ballot_sync(0xffffffffu, neg);
        if (lane == 0) g_wt[(tap * 8 + j) * O_ + o] = bal;
        if (v == 0.f) {
            int idx = atomicAdd(&g_wz_count, 1);
            if (idx < 64) g_wz_list[idx] = (o * C_ + c) * 9 + tap;
        }
    }
    // per-tap popcount (warp j owns word j)
    if (lane == 0) {
#pragma unroll
        for (int tap = 0; tap < 9; tap++)
            atomicAdd(&g_pw[o * 9 + tap], __popc(g_wt[(tap * 8 + j) * O_ + o]));
    }
    __shared__ float red[256];
    red[tid] = s;
    __syncthreads();
    for (int st = 128; st > 0; st >>= 1) {
        if (tid < st) red[tid] += red[tid + st];
        __syncthreads();
    }
    if (tid == 0) g_m[o] = red[0] / 2304.f;
}

// ---------------- K2b: zero pw ----------------
__global__ void k_zpw() {
    int t = blockIdx.x * blockDim.x + threadIdx.x;
    if (t < O_ * 9) g_pw[t] = 0;
}

// ---------------- K3: HYBRID conv: IMMA (taps 0,1) + popcount (taps 2..8) -------
// CTA 128Mx128N, 8 warps (2Mx4N), grid = 784*2.
// SMEM words: A8 128x36 | B8 128x36 | Xb 7*8*128 | Wb 7*8*128  = 23552 w = 94208 B
#define RS8     36
#define B8_OFF  (128 * RS8)            // 4608
#define XB_OFF  (2 * 128 * RS8)        // 9216
#define WB_OFF  (XB_OFF + 7 * 8 * 128) // 16384
#define CONV_SMEM ((WB_OFF + 7 * 8 * 128) * 4)

__global__ __launch_bounds__(256, 2) void k_conv(float* __restrict__ out) {
    extern __shared__ unsigned smw[];

    int tid  = threadIdx.x;
    int wid  = tid >> 5;
    int lane = tid & 31;
    int g    = lane >> 2;
    int tig  = lane & 3;

    int mBase = (blockIdx.x >> 1) * 128;
    int nBase = (blockIdx.x & 1) * 128;

    int m_off = (wid & 1) * 64;
    int n_off = (wid >> 1) * 32;

    int acc[4][4][4];
#pragma unroll
    for (int mi = 0; mi < 4; mi++)
#pragma unroll
        for (int ni = 0; ni < 4; ni++)
#pragma unroll
            for (int k = 0; k < 4; k++) acc[mi][ni][k] = 0;

    const uint4 z4 = make_uint4(0u, 0u, 0u, 0u);

    // ---- fill bitpacked tiles (ALU taps 2..8) ----
    for (int u = tid; u < 7 * 128; u += 256) {
        int t7 = u >> 7, row = u & 127;
        int tap = t7 + 2;
        int gp = mBase + row;
        int fn = gp / PIX;
        int fp = gp - fn * PIX;
        int fh = fp / HW_, fw = fp - (fp / HW_) * HW_;
        int h2 = fh + tap / 3 - 1, w2 = fw + tap % 3 - 1;
        uint4 lo = z4, hi = z4;
        if ((unsigned)h2 < HW_ && (unsigned)w2 < HW_) {
            const uint4* src = (const uint4*)&g_xbits[((size_t)fn * PIX + h2 * HW_ + w2) * 8];
            lo = src[0]; hi = src[1];
        }
        unsigned* d = &smw[XB_OFF + t7 * 1024 + row];
        d[0] = lo.x; d[128] = lo.y; d[256] = lo.z; d[384] = lo.w;
        d[512] = hi.x; d[640] = hi.y; d[768] = hi.z; d[896] = hi.w;
    }
    for (int v = tid; v < 7 * 8 * 32; v += 256) {
        int q = v >> 5;                   // t7*8 + j
        int c4 = (v & 31) * 4;
        int t7 = q >> 3, j = q & 7;
        *(uint4*)&smw[WB_OFF + q * 128 + c4] =
            *(const uint4*)&g_wt[((t7 + 2) * 8 + j) * O_ + nBase + c4];
    }

    // ---- fill-role mapping for int8 tiles ----
    int pix_i = tid >> 1;
    int half  = tid & 1;
    int gp = mBase + pix_i;
    int fn = gp / PIX;
    int fp = gp - fn * PIX;
    int fh = fp / HW_, fw = fp - (fp / HW_) * HW_;

    // ---- tensor stage: taps 0,1 ; K=256 each, in 2 halves of 128 ----
#pragma unroll 1
    for (int tt = 0; tt < 2; tt++) {
        int h2 = fh - 1, w2 = fw + tt - 1;
        bool valid = ((unsigned)h2 < HW_) && ((unsigned)w2 < HW_);
        const signed char* srcA = &g_xb[((size_t)fn * PIX + h2 * HW_ + w2) * C_];
        const signed char* srcB = &g_wb[((size_t)tt * O_ + nBase + pix_i) * C_];
#pragma unroll 1
        for (int hf = 0; hf < 2; hf++) {
            __syncthreads();
            const uint4* sA = (const uint4*)(srcA + hf * 128 + half * 64);
            const uint4* sB = (const uint4*)(srcB + hf * 128 + half * 64);
#pragma unroll
            for (int j2 = 0; j2 < 4; j2++) {
                *(uint4*)&smw[pix_i * RS8 + half * 16 + j2 * 4] = valid ? sA[j2] : z4;
                *(uint4*)&smw[B8_OFF + pix_i * RS8 + half * 16 + j2 * 4] = sB[j2];
            }
            __syncthreads();
#pragma unroll
            for (int kc = 0; kc < 4; kc++) {
                unsigned a[4][4], bfr[4][2];
                int kw0 = kc * 8 + tig;
#pragma unroll
                for (int mi = 0; mi < 4; mi++) {
                    int base = (m_off + mi * 16 + g) * RS8 + kw0;
                    a[mi][0] = smw[base];
                    a[mi][1] = smw[base + 8 * RS8];
                    a[mi][2] = smw[base + 4];
                    a[mi][3] = smw[base + 8 * RS8 + 4];
                }
#pragma unroll
                for (int ni = 0; ni < 4; ni++) {
                    int base = B8_OFF + (n_off + ni * 8 + g) * RS8 + kw0;
                    bfr[ni][0] = smw[base];
                    bfr[ni][1] = smw[base + 4];
                }
#pragma unroll
                for (int mi = 0; mi < 4; mi++)
#pragma unroll
                    for (int ni = 0; ni < 4; ni++)
                        imma16832(acc[mi][ni], a[mi], bfr[ni]);
            }
        }
    }

    // ---- popcount stage: taps 2..8 from bitpacked SMEM tiles ----
#pragma unroll 1
    for (int t7 = 0; t7 < 7; t7++) {
#pragma unroll 2
        for (int w8 = 0; w8 < 8; w8++) {
            const unsigned* xb = &smw[XB_OFF + (t7 * 8 + w8) * 128];
            const unsigned* wb = &smw[WB_OFF + (t7 * 8 + w8) * 128];
            unsigned xr[8], wc[8];
#pragma unroll
            for (int mi = 0; mi < 4; mi++) {
                xr[mi * 2]     = xb[m_off + mi * 16 + g];
                xr[mi * 2 + 1] = xb[m_off + mi * 16 + 8 + g];
            }
#pragma unroll
            for (int ni = 0; ni < 4; ni++) {
                wc[ni * 2]     = wb[n_off + ni * 8 + tig * 2];
                wc[ni * 2 + 1] = wb[n_off + ni * 8 + tig * 2 + 1];
            }
#pragma unroll
            for (int mi = 0; mi < 4; mi++)
#pragma unroll
                for (int ni = 0; ni < 4; ni++) {
                    acc[mi][ni][0] -= 2 * __popc(xr[mi * 2]     ^ wc[ni * 2]);
                    acc[mi][ni][1] -= 2 * __popc(xr[mi * 2]     ^ wc[ni * 2 + 1]);
                    acc[mi][ni][2] -= 2 * __popc(xr[mi * 2 + 1] ^ wc[ni * 2]);
                    acc[mi][ni][3] -= 2 * __popc(xr[mi * 2 + 1] ^ wc[ni * 2 + 1]);
                }
        }
    }

    // ---- epilogue: +1792 offset, padding corrections for ALU taps, scale, store ----
#pragma unroll
    for (int mi = 0; mi < 4; mi++) {
#pragma unroll
        for (int h = 0; h < 2; h++) {
            int row = m_off + mi * 16 + h * 8 + g;
            int gpp = mBase + row;
            int n = gpp / PIX;
            int p = gpp - n * PIX;
            int oh = p / HW_, ow = p - (p / HW_) * HW_;
            float al = alpha_of(n);
            bool top = (oh == 0), bot = (oh == HW_ - 1);
            bool lef = (ow == 0), rig = (ow == HW_ - 1);
            bool edge = top || bot || lef || rig;
            float* ob = out + (size_t)n * O_ * PIX + p;
#pragma unroll
            for (int ni = 0; ni < 4; ni++) {
#pragma unroll
                for (int j = 0; j < 2; j++) {
                    int o = nBase + n_off + ni * 8 + tig * 2 + j;
                    int S = acc[mi][ni][h * 2 + j] + 1792;
                    if (edge) {
                        const int* pwo = &g_pw[o * 9];
                        if (top || rig) S -= 256 - 2 * __ldg(pwo + 2);
                        if (lef)        S -= 256 - 2 * __ldg(pwo + 3);
                        if (rig)        S -= 256 - 2 * __ldg(pwo + 5);
                        if (bot || lef) S -= 256 - 2 * __ldg(pwo + 6);
                        if (bot)        S -= 256 - 2 * __ldg(pwo + 7);
                        if (bot || rig) S -= 256 - 2 * __ldg(pwo + 8);
                    }
                    ob[(size_t)o * PIX] = al * __ldg(&g_m[o]) * (float)S;
                }
            }
        }
    }
}

// ---------------- K4: exact correction for x==0 ----------------
__global__ void k_xzero(float* __restrict__ out) {
    int zc = g_xz_count;
    if (zc > 4096) zc = 4096;
    long total = (long)zc * 2304;
    for (long i = (long)blockIdx.x * blockDim.x + threadIdx.x; i < total;
         i += (long)gridDim.x * blockDim.x) {
        int z = (int)(i / 2304);
        int q = (int)(i % 2304);
        int o = q / 9, tap = q % 9;
        int li = g_xz_list[z];
        int pix = li % PIX;
        int ch = (li / PIX) & 255;
        int n = li / (PIX * C_);
        int h = pix / HW_, wv = pix % HW_;
        int kh = tap / 3, kw = tap % 3;
        int oh = h + 1 - kh, ow = wv + 1 - kw;
        if ((unsigned)oh < HW_ && (unsigned)ow < HW_) {
            float bw = (float)g_wb[((size_t)tap * O_ + o) * C_ + ch];
            atomicAdd(&out[((size_t)(n * O_ + o)) * PIX + oh * HW_ + ow],
                      -bw * alpha_of(n) * g_m[o]);
        }
    }
}

// ---------------- K5: exact correction for w==0 ----------------
__global__ void k_wzero(const float* __restrict__ x, float* __restrict__ out) {
    int zc = g_wz_count;
    if (zc > 64) zc = 64;
    long total = (long)zc * N_ * PIX;
    for (long i = (long)blockIdx.x * blockDim.x + threadIdx.x; i < total;
         i += (long)gridDim.x * blockDim.x) {
        int z = (int)(i / ((long)N_ * PIX));
        int rte = (int)(i % ((long)N_ * PIX));
        int n = rte / PIX, pix = rte % PIX;
        int oh = pix / HW_, ow = pix % HW_;
        int li = g_wz_list[z];
        int tap = li % 9;
        int ch = (li / 9) & 255;
        int o = li / (9 * C_);
        int kh = tap / 3, kw = tap % 3;
        int ih = oh - 1 + kh, iw = ow - 1 + kw;
        if ((unsigned)ih < HW_ && (unsigned)iw < HW_) {
            float xv = x[((size_t)(n * C_ + ch)) * PIX + ih * HW_ + iw];
            if (xv != 0.f) {
                float bx = (xv < 0.f) ? -1.f : 1.f;
                atomicAdd(&out[((size_t)(n * O_ + o)) * PIX + pix],
                          -bx * alpha_of(n) * g_m[o]);
            }
        }
    }
}

// ---------------- launch ----------------
extern "C" void kernel_launch(void* const* d_in, const int* in_sizes, int n_in,
                              void* d_out, int out_size) {
    const float* x = (const float*)d_in[0];
    const float* w = (const float*)d_in[1];
    float* out = (float*)d_out;

    cudaFuncSetAttribute(k_conv, cudaFuncAttributeMaxDynamicSharedMemorySize, CONV_SMEM);

    k_zero<<<9, 256>>>();
    k_zpw<<<9, 256>>>();
    k_packx<<<416, 256>>>(x);
    k_packw<<<256, 256>>>(w);
    k_conv<<<1568, 256, CONV_SMEM>>>(out);
    k_xzero<<<64, 256>>>(out);
    k_wzero<<<128, 256>>>(x, out);
}